// round 3
// baseline (speedup 1.0000x reference)
#include <cuda_runtime.h>
#include <cstdint>
#include <cstddef>

#define HH 4
#define BB 32
#define NN 14
#define FF 1024

typedef unsigned long long ull;

__device__ __forceinline__ ull pk2(float a, float b) {
    ull r; asm("mov.b64 %0, {%1,%2};" : "=l"(r) : "f"(a), "f"(b)); return r;
}
__device__ __forceinline__ ull ffma2(ull a, ull b, ull c) {
    ull d; asm("fma.rn.f32x2 %0, %1, %2, %3;" : "=l"(d) : "l"(a), "l"(b), "l"(c)); return d;
}
__device__ __forceinline__ float2 upk2(ull a) {
    float2 f; asm("mov.b64 {%0,%1}, %2;" : "=f"(f.x), "=f"(f.y) : "l"(a)); return f;
}

// Scratch (allocation-free rules: __device__ globals)
__device__ float g_Wh[HH*BB*NN*FF];        // 7 MB
__device__ float g_hp[HH*BB*NN*FF];        // 7 MB
__device__ float g_part[64*BB*FF];         // 8 MB split-K partials

// ---------------------------------------------------------------------------
// K1: Wh[h,b,n,o] = sum_i x[b,n,i] * W[h,b,i,o]
// One block per (h,b). x[b] staged in smem as duplicated f32 pairs (u64),
// layout xs[i*14 + n] so LDS.128 fetches two rows' packed values at once.
// Each thread owns 4 output columns (tid*4..+3), 14 rows -> 28 f32x2 accs.
// ---------------------------------------------------------------------------
__global__ void __launch_bounds__(256) k1(const float* __restrict__ x,
                                          const float* __restrict__ W) {
    extern __shared__ ull xs[];            // [1024][14] duplicated pairs (112 KB)
    int hb = blockIdx.x;
    int b  = hb & 31;
    int tid = threadIdx.x;

    const float* xb = x + (size_t)b * NN * FF;
    for (int idx = tid; idx < NN*FF; idx += 256) {
        int n = idx >> 10;
        int i = idx & 1023;
        float v = xb[idx];
        xs[i*NN + n] = pk2(v, v);
    }
    __syncthreads();

    const float4* Wt = (const float4*)(W + (size_t)hb * FF * FF);
    ull acc[NN][2];
#pragma unroll
    for (int n = 0; n < NN; n++) { acc[n][0] = 0ull; acc[n][1] = 0ull; }

#pragma unroll 4
    for (int i = 0; i < FF; i++) {
        float4 w = Wt[i*256 + tid];
        ull w01 = pk2(w.x, w.y);
        ull w23 = pk2(w.z, w.w);
        const ulonglong2* xr = (const ulonglong2*)(xs + i*NN);
#pragma unroll
        for (int n2 = 0; n2 < 7; n2++) {
            ulonglong2 xx = xr[n2];   // broadcast LDS.128: rows 2*n2, 2*n2+1
            acc[2*n2  ][0] = ffma2(w01, xx.x, acc[2*n2  ][0]);
            acc[2*n2  ][1] = ffma2(w23, xx.x, acc[2*n2  ][1]);
            acc[2*n2+1][0] = ffma2(w01, xx.y, acc[2*n2+1][0]);
            acc[2*n2+1][1] = ffma2(w23, xx.y, acc[2*n2+1][1]);
        }
    }

    float* o = g_Wh + (size_t)hb * NN * FF;
#pragma unroll
    for (int n = 0; n < NN; n++) {
        float2 p0 = upk2(acc[n][0]);
        float2 p1 = upk2(acc[n][1]);
        ((float4*)(o + n*FF))[tid] = make_float4(p0.x, p0.y, p1.x, p1.y);
    }
}

// ---------------------------------------------------------------------------
// K2: attention scores + softmax(axis=n) + h_prime = att @ Wh
// One block per (h,b), 448 threads = 14 warps (warp w handles row w dots).
// ---------------------------------------------------------------------------
__global__ void __launch_bounds__(448) k2(const float* __restrict__ adj,
                                          const float* __restrict__ a) {
    int hb = blockIdx.x;
    int b  = hb & 31;
    __shared__ float s1[NN], s2[NN];
    __shared__ float att_s[NN][NN];
    int tid = threadIdx.x;
    int w = tid >> 5, lane = tid & 31;
    const float* WhB = g_Wh + (size_t)hb * NN * FF;

    {   // Wh1[n] = Wh[n,:]·a1, Wh2[n] = Wh[n,:]·a2  (warp n)
        const float* a1 = a + (size_t)hb * 2 * FF;
        const float* a2 = a1 + FF;
        const float* row = WhB + w * FF;
        float p1 = 0.f, p2 = 0.f;
        for (int o = lane; o < FF; o += 32) {
            float wv = row[o];
            p1 += wv * a1[o];
            p2 += wv * a2[o];
        }
#pragma unroll
        for (int d = 16; d; d >>= 1) {
            p1 += __shfl_down_sync(0xffffffffu, p1, d);
            p2 += __shfl_down_sync(0xffffffffu, p2, d);
        }
        if (lane == 0) { s1[w] = p1; s2[w] = p2; }
    }
    __syncthreads();

    // softmax over n (axis=2 of (H,B,N,N)) — thread m handles column m
    if (tid < NN) {
        int m = tid;
        float col[NN];
        float mx = -1e30f;
#pragma unroll
        for (int n = 0; n < NN; n++) {
            float e = s1[n] + s2[m];
            e = e > 0.f ? e : 0.2f * e;                       // leaky_relu
            e = (adj[b*NN*NN + n*NN + m] > 0.f) ? e : -9.0e15f;
            col[n] = e;
            mx = fmaxf(mx, e);
        }
        float sm = 0.f;
#pragma unroll
        for (int n = 0; n < NN; n++) { col[n] = expf(col[n] - mx); sm += col[n]; }
        float inv = 1.f / sm;
#pragma unroll
        for (int n = 0; n < NN; n++) att_s[n][m] = col[n] * inv;
    }
    __syncthreads();

    // h_prime[n,o] = sum_m att[n,m] * Wh[m,o]
    float* hpB = g_hp + (size_t)hb * NN * FF;
    for (int o = tid; o < FF; o += 448) {
        float wv[NN];
#pragma unroll
        for (int m = 0; m < NN; m++) wv[m] = WhB[m*FF + o];
#pragma unroll
        for (int n = 0; n < NN; n++) {
            float sacc = 0.f;
#pragma unroll
            for (int m = 0; m < NN; m++) sacc += att_s[n][m] * wv[m];
            hpB[n*FF + o] = sacc;
        }
    }
}

// ---------------------------------------------------------------------------
// K3: out_partial[p][b][o] = sum over k-range of hp[h,b,k] * fc_w[h,o,k]
// grid (4 o-tiles of 256, 4 h, 16 k-splits of 896). Block tile 32b x 256o,
// thread tile 8b x 8o (4 f32x2 col-pairs). fc_w tile stored transposed in
// smem with even-XOR swizzle -> conflict-free LDS.64 loads and STS.
// ---------------------------------------------------------------------------
__global__ void __launch_bounds__(128) k3(const float* __restrict__ fc_w) {
    __shared__ float w_s[32][256];
    __shared__ float hp_s[32][34];
    int t  = threadIdx.x;
    int tx = t & 31, ty = t >> 5;          // ty in 0..3
    int o0 = blockIdx.x * 256;
    int h  = blockIdx.y;
    int f0 = blockIdx.z * 896;
    const float* fw = fc_w + (size_t)h * FF * (NN*FF);
    const float* hp = g_hp + (size_t)h * BB * (NN*FF);

    ull acc[8][4];
#pragma unroll
    for (int i = 0; i < 8; i++)
#pragma unroll
        for (int j = 0; j < 4; j++) acc[i][j] = 0ull;

    int rr = t >> 3, kq = t & 7;

    for (int ch = 0; ch < 28; ch++) {
        int kb = f0 + ch * 32;
        // stage fc_w tile (256 o x 32 k), transposed + XOR-swizzled
#pragma unroll
        for (int rep = 0; rep < 16; rep++) {
            int orow = rr + rep * 16;
            float4 v = *(const float4*)(fw + (size_t)(o0 + orow)*(NN*FF) + kb + kq*4);
            int k0 = kq * 4;
            w_s[k0+0][orow ^ ((k0+0) & 30)] = v.x;
            w_s[k0+1][orow ^ ((k0+1) & 30)] = v.y;
            w_s[k0+2][orow ^ ((k0+2) & 30)] = v.z;
            w_s[k0+3][orow ^ ((k0+3) & 30)] = v.w;
        }
        // stage hp tile (32 b x 32 k), transposed
#pragma unroll
        for (int rep = 0; rep < 2; rep++) {
            int br = rr + rep * 16;
            float4 v = *(const float4*)(hp + (size_t)br*(NN*FF) + kb + kq*4);
            int k0 = kq * 4;
            hp_s[k0+0][br] = v.x;
            hp_s[k0+1][br] = v.y;
            hp_s[k0+2][br] = v.z;
            hp_s[k0+3][br] = v.w;
        }
        __syncthreads();

#pragma unroll 8
        for (int k = 0; k < 32; k++) {
            int s  = k & 30;
            int pc = (2*tx) ^ s;
            ull w0 = *(const ull*)&w_s[k][pc];
            ull w1 = *(const ull*)&w_s[k][64  + pc];
            ull w2 = *(const ull*)&w_s[k][128 + pc];
            ull w3 = *(const ull*)&w_s[k][192 + pc];
            const float2* hr = (const float2*)&hp_s[k][ty*8];
            float2 h01 = hr[0], h23 = hr[1], h45 = hr[2], h67 = hr[3];
            ull xb[8];
            xb[0] = pk2(h01.x, h01.x); xb[1] = pk2(h01.y, h01.y);
            xb[2] = pk2(h23.x, h23.x); xb[3] = pk2(h23.y, h23.y);
            xb[4] = pk2(h45.x, h45.x); xb[5] = pk2(h45.y, h45.y);
            xb[6] = pk2(h67.x, h67.x); xb[7] = pk2(h67.y, h67.y);
#pragma unroll
            for (int bi = 0; bi < 8; bi++) {
                acc[bi][0] = ffma2(w0, xb[bi], acc[bi][0]);
                acc[bi][1] = ffma2(w1, xb[bi], acc[bi][1]);
                acc[bi][2] = ffma2(w2, xb[bi], acc[bi][2]);
                acc[bi][3] = ffma2(w3, xb[bi], acc[bi][3]);
            }
        }
        __syncthreads();
    }

    float* pt = g_part + ((size_t)(h*16 + blockIdx.z)) * BB * FF;
#pragma unroll
    for (int bi = 0; bi < 8; bi++) {
        int b = ty * 8 + bi;
#pragma unroll
        for (int p = 0; p < 4; p++) {
            float2 v = upk2(acc[bi][p]);
            int oc = o0 + p*64 + 2*tx;
            pt[b*FF + oc]     = v.x;
            pt[b*FF + oc + 1] = v.y;
        }
    }
}

// ---------------------------------------------------------------------------
// K4: out[b,o] = log_softmax_o( sum_p part[p][b][o] + sum_h fc_b[h][o] )
// ---------------------------------------------------------------------------
__global__ void __launch_bounds__(256) k4(const float* __restrict__ fc_b,
                                          float* __restrict__ out) {
    int b = blockIdx.x, t = threadIdx.x;
    __shared__ float v[FF];
    __shared__ float red[256];

    for (int o = t; o < FF; o += 256) {
        float s = 0.f;
#pragma unroll
        for (int p = 0; p < 64; p++) s += g_part[(size_t)p*BB*FF + b*FF + o];
        s += fc_b[o] + fc_b[FF + o] + fc_b[2*FF + o] + fc_b[3*FF + o];
        v[o] = s;
    }
    __syncthreads();

    float mx = -1e30f;
    for (int o = t; o < FF; o += 256) mx = fmaxf(mx, v[o]);
    red[t] = mx; __syncthreads();
    for (int st = 128; st > 0; st >>= 1) {
        if (t < st) red[t] = fmaxf(red[t], red[t+st]);
        __syncthreads();
    }
    mx = red[0]; __syncthreads();

    float sm = 0.f;
    for (int o = t; o < FF; o += 256) sm += expf(v[o] - mx);
    red[t] = sm; __syncthreads();
    for (int st = 128; st > 0; st >>= 1) {
        if (t < st) red[t] += red[t+st];
        __syncthreads();
    }
    float lse = logf(red[0]) + mx;

    for (int o = t; o < FF; o += 256) out[b*FF + o] = v[o] - lse;
}

// ---------------------------------------------------------------------------
extern "C" void kernel_launch(void* const* d_in, const int* in_sizes, int n_in,
                              void* d_out, int out_size) {
    const float *x = nullptr, *adj = nullptr, *W = nullptr, *a = nullptr;
    const float *fcw = nullptr, *fcb = nullptr;
    for (int i = 0; i < n_in; i++) {
        switch (in_sizes[i]) {
            case 458752:    x   = (const float*)d_in[i]; break;  // x (32,14,1024)
            case 6272:      adj = (const float*)d_in[i]; break;  // adj (32,14,14)
            case 134217728: W   = (const float*)d_in[i]; break;  // W (4,32,1024,1024)
            case 262144:    a   = (const float*)d_in[i]; break;  // a (4,32,2048,1)
            case 58720256:  fcw = (const float*)d_in[i]; break;  // fc_w (4,1024,14336)
            case 4096:      fcb = (const float*)d_in[i]; break;  // fc_b (4,1024)
        }
    }
    cudaFuncSetAttribute(k1, cudaFuncAttributeMaxDynamicSharedMemorySize, NN*FF*8);
    k1<<<HH*BB, 256, NN*FF*8>>>(x, W);
    k2<<<HH*BB, 448>>>(adj, a);
    k3<<<dim3(4, 4, 16), 128>>>(fcw);
    k4<<<BB, 256>>>(fcb, (float*)d_out);
}

// round 4
// speedup vs baseline: 1.1021x; 1.1021x over previous
#include <cuda_runtime.h>
#include <cstdint>
#include <cstddef>

#define HH 4
#define BB 32
#define NN 14
#define FF 1024

typedef unsigned long long ull;

__device__ __forceinline__ ull pk2(float a, float b) {
    ull r; asm("mov.b64 %0, {%1,%2};" : "=l"(r) : "f"(a), "f"(b)); return r;
}
__device__ __forceinline__ ull ffma2(ull a, ull b, ull c) {
    ull d; asm("fma.rn.f32x2 %0, %1, %2, %3;" : "=l"(d) : "l"(a), "l"(b), "l"(c)); return d;
}
__device__ __forceinline__ float2 upk2(ull a) {
    float2 f; asm("mov.b64 {%0,%1}, %2;" : "=f"(f.x), "=f"(f.y) : "l"(a)); return f;
}

// Scratch (allocation-free rules: __device__ globals)
__device__ float g_Wh[HH*BB*NN*FF];        // 7 MB
__device__ float g_hp[HH*BB*NN*FF];        // 7 MB
__device__ float g_part[64*BB*FF];         // 8 MB split-K partials

// ---------------------------------------------------------------------------
// K1: Wh[h,b,n,o] = sum_i x[b,n,i] * W[h,b,i,o]
// One block per (h,b). x[b] staged in smem as duplicated f32 pairs (u64),
// layout xs[i*14 + n]. W row loaded directly as ulonglong2 — the raw 16 bytes
// ARE the packed (w0,w1),(w2,w3) f32x2 operands; zero pack instructions.
// unroll 8 -> 8 LDG.128/thread in flight -> DRAM-saturating MLP.
// ---------------------------------------------------------------------------
__global__ void __launch_bounds__(256) k1(const float* __restrict__ x,
                                          const float* __restrict__ W) {
    extern __shared__ ull xs[];            // [1024][14] duplicated pairs (112 KB)
    int hb = blockIdx.x;
    int b  = hb & 31;
    int tid = threadIdx.x;

    const float* xb = x + (size_t)b * NN * FF;
    // vectorized staging: 14 iterations of LDG.128 + 4 STS.64
    for (int idx = tid; idx < NN*FF/4; idx += 256) {
        int n  = idx >> 8;
        int i4 = (idx & 255) * 4;
        float4 v = *(const float4*)(xb + n*FF + i4);
        xs[(i4+0)*NN + n] = pk2(v.x, v.x);
        xs[(i4+1)*NN + n] = pk2(v.y, v.y);
        xs[(i4+2)*NN + n] = pk2(v.z, v.z);
        xs[(i4+3)*NN + n] = pk2(v.w, v.w);
    }
    __syncthreads();

    const ulonglong2* Wt = (const ulonglong2*)(W + (size_t)hb * FF * FF);
    ull acc[NN][2];
#pragma unroll
    for (int n = 0; n < NN; n++) { acc[n][0] = 0ull; acc[n][1] = 0ull; }

#pragma unroll 8
    for (int i = 0; i < FF; i++) {
        ulonglong2 w = Wt[i*256 + tid];    // w.x = pk2(W[..2c],W[..2c+1]) bitwise
        const ulonglong2* xr = (const ulonglong2*)(xs + i*NN);
#pragma unroll
        for (int n2 = 0; n2 < 7; n2++) {
            ulonglong2 xx = xr[n2];        // broadcast LDS.128: rows 2*n2, 2*n2+1
            acc[2*n2  ][0] = ffma2(w.x, xx.x, acc[2*n2  ][0]);
            acc[2*n2  ][1] = ffma2(w.y, xx.x, acc[2*n2  ][1]);
            acc[2*n2+1][0] = ffma2(w.x, xx.y, acc[2*n2+1][0]);
            acc[2*n2+1][1] = ffma2(w.y, xx.y, acc[2*n2+1][1]);
        }
    }

    float* o = g_Wh + (size_t)hb * NN * FF;
#pragma unroll
    for (int n = 0; n < NN; n++) {
        float2 p0 = upk2(acc[n][0]);
        float2 p1 = upk2(acc[n][1]);
        ((float4*)(o + n*FF))[tid] = make_float4(p0.x, p0.y, p1.x, p1.y);
    }
}

// ---------------------------------------------------------------------------
// K2: attention scores + softmax(axis=n) + h_prime = att @ Wh
// One block per (h,b), 448 threads = 14 warps (warp w handles row w dots).
// ---------------------------------------------------------------------------
__global__ void __launch_bounds__(448) k2(const float* __restrict__ adj,
                                          const float* __restrict__ a) {
    int hb = blockIdx.x;
    int b  = hb & 31;
    __shared__ float s1[NN], s2[NN];
    __shared__ float att_s[NN][NN];
    int tid = threadIdx.x;
    int w = tid >> 5, lane = tid & 31;
    const float* WhB = g_Wh + (size_t)hb * NN * FF;

    {   // Wh1[n] = Wh[n,:]·a1, Wh2[n] = Wh[n,:]·a2  (warp n)
        const float* a1 = a + (size_t)hb * 2 * FF;
        const float* a2 = a1 + FF;
        const float* row = WhB + w * FF;
        float p1 = 0.f, p2 = 0.f;
        for (int o = lane; o < FF; o += 32) {
            float wv = row[o];
            p1 += wv * a1[o];
            p2 += wv * a2[o];
        }
#pragma unroll
        for (int d = 16; d; d >>= 1) {
            p1 += __shfl_down_sync(0xffffffffu, p1, d);
            p2 += __shfl_down_sync(0xffffffffu, p2, d);
        }
        if (lane == 0) { s1[w] = p1; s2[w] = p2; }
    }
    __syncthreads();

    // softmax over n (axis=2 of (H,B,N,N)) — thread m handles column m
    if (tid < NN) {
        int m = tid;
        float col[NN];
        float mx = -1e30f;
#pragma unroll
        for (int n = 0; n < NN; n++) {
            float e = s1[n] + s2[m];
            e = e > 0.f ? e : 0.2f * e;                       // leaky_relu
            e = (adj[b*NN*NN + n*NN + m] > 0.f) ? e : -9.0e15f;
            col[n] = e;
            mx = fmaxf(mx, e);
        }
        float sm = 0.f;
#pragma unroll
        for (int n = 0; n < NN; n++) { col[n] = expf(col[n] - mx); sm += col[n]; }
        float inv = 1.f / sm;
#pragma unroll
        for (int n = 0; n < NN; n++) att_s[n][m] = col[n] * inv;
    }
    __syncthreads();

    // h_prime[n,o] = sum_m att[n,m] * Wh[m,o]
    float* hpB = g_hp + (size_t)hb * NN * FF;
    for (int o = tid; o < FF; o += 448) {
        float wv[NN];
#pragma unroll
        for (int m = 0; m < NN; m++) wv[m] = WhB[m*FF + o];
#pragma unroll
        for (int n = 0; n < NN; n++) {
            float sacc = 0.f;
#pragma unroll
            for (int m = 0; m < NN; m++) sacc += att_s[n][m] * wv[m];
            hpB[n*FF + o] = sacc;
        }
    }
}

// ---------------------------------------------------------------------------
// K3: out_partial[p][b][o] = sum over k-range of hp[h,b,k] * fc_w[h,o,k]
// grid (4 o-tiles of 256, 4 h, 16 k-splits of 896). Block tile 32b x 256o,
// thread tile 8b x 8o. fc_w tile transposed + XOR-swizzled in smem
// (conflict-free LDS.64). hp tile stored PRE-DUPLICATED as u64 pairs so the
// inner loop needs zero pack instructions (4 LDS.128 broadcast per k).
// ---------------------------------------------------------------------------
__global__ void __launch_bounds__(128) k3(const float* __restrict__ fc_w) {
    __shared__ float w_s[32][256];
    __shared__ ull hp_s[32][34];           // [k][b] duplicated pairs, pad->16B align
    int t  = threadIdx.x;
    int tx = t & 31, ty = t >> 5;          // ty in 0..3
    int tx2 = 2 * tx;
    int o0 = blockIdx.x * 256;
    int h  = blockIdx.y;
    int f0 = blockIdx.z * 896;
    const float* fw = fc_w + (size_t)h * FF * (NN*FF);
    const float* hp = g_hp + (size_t)h * BB * (NN*FF);

    ull acc[8][4];
#pragma unroll
    for (int i = 0; i < 8; i++)
#pragma unroll
        for (int j = 0; j < 4; j++) acc[i][j] = 0ull;

    int rr = t >> 3, kq = t & 7;

    for (int ch = 0; ch < 28; ch++) {
        int kb = f0 + ch * 32;
        // stage fc_w tile (256 o x 32 k), transposed + XOR-swizzled
#pragma unroll
        for (int rep = 0; rep < 16; rep++) {
            int orow = rr + rep * 16;
            float4 v = *(const float4*)(fw + (size_t)(o0 + orow)*(NN*FF) + kb + kq*4);
            int k0 = kq * 4;
            w_s[k0+0][orow ^ ((k0+0) & 30)] = v.x;
            w_s[k0+1][orow ^ ((k0+1) & 30)] = v.y;
            w_s[k0+2][orow ^ ((k0+2) & 30)] = v.z;
            w_s[k0+3][orow ^ ((k0+3) & 30)] = v.w;
        }
        // stage hp tile (32 b x 32 k), transposed + duplicated pairs
#pragma unroll
        for (int rep = 0; rep < 2; rep++) {
            int br = rr + rep * 16;
            float4 v = *(const float4*)(hp + (size_t)br*(NN*FF) + kb + kq*4);
            int k0 = kq * 4;
            hp_s[k0+0][br] = pk2(v.x, v.x);
            hp_s[k0+1][br] = pk2(v.y, v.y);
            hp_s[k0+2][br] = pk2(v.z, v.z);
            hp_s[k0+3][br] = pk2(v.w, v.w);
        }
        __syncthreads();

#pragma unroll 8
        for (int k = 0; k < 32; k++) {
            int s  = k & 30;
            int pc = tx2 ^ s;
            ull w0 = *(const ull*)&w_s[k][pc];
            ull w1 = *(const ull*)&w_s[k][64  + pc];
            ull w2 = *(const ull*)&w_s[k][128 + pc];
            ull w3 = *(const ull*)&w_s[k][192 + pc];
            const ulonglong2* hr = (const ulonglong2*)&hp_s[k][ty*8];
            ulonglong2 x01 = hr[0], x23 = hr[1], x45 = hr[2], x67 = hr[3];
            ull xb[8] = {x01.x, x01.y, x23.x, x23.y, x45.x, x45.y, x67.x, x67.y};
#pragma unroll
            for (int bi = 0; bi < 8; bi++) {
                acc[bi][0] = ffma2(w0, xb[bi], acc[bi][0]);
                acc[bi][1] = ffma2(w1, xb[bi], acc[bi][1]);
                acc[bi][2] = ffma2(w2, xb[bi], acc[bi][2]);
                acc[bi][3] = ffma2(w3, xb[bi], acc[bi][3]);
            }
        }
        __syncthreads();
    }

    float* pt = g_part + ((size_t)(h*16 + blockIdx.z)) * BB * FF;
#pragma unroll
    for (int bi = 0; bi < 8; bi++) {
        int b = ty * 8 + bi;
#pragma unroll
        for (int p = 0; p < 4; p++) {
            float2 v = upk2(acc[bi][p]);
            int oc = o0 + p*64 + tx2;
            pt[b*FF + oc]     = v.x;
            pt[b*FF + oc + 1] = v.y;
        }
    }
}

// ---------------------------------------------------------------------------
// K4: out[b,o] = log_softmax_o( sum_p part[p][b][o] + sum_h fc_b[h][o] )
// float4 per thread (256 thr x 4 o = 1024), unrolled 64-way partial sum for
// MLP, shuffle+smem block reductions.
// ---------------------------------------------------------------------------
__global__ void __launch_bounds__(256) k4(const float* __restrict__ fc_b,
                                          float* __restrict__ out) {
    int b = blockIdx.x, t = threadIdx.x;
    int lane = t & 31, wrp = t >> 5;
    __shared__ float red[8];

    float4 s = make_float4(0.f, 0.f, 0.f, 0.f);
    const float4* gp = (const float4*)g_part;
#pragma unroll 16
    for (int p = 0; p < 64; p++) {
        float4 v = gp[(size_t)(p*BB + b) * (FF/4) + t];
        s.x += v.x; s.y += v.y; s.z += v.z; s.w += v.w;
    }
    const float4* fb = (const float4*)fc_b;
#pragma unroll
    for (int h = 0; h < HH; h++) {
        float4 v = fb[h*(FF/4) + t];
        s.x += v.x; s.y += v.y; s.z += v.z; s.w += v.w;
    }

    // block max
    float m = fmaxf(fmaxf(s.x, s.y), fmaxf(s.z, s.w));
#pragma unroll
    for (int d = 16; d; d >>= 1) m = fmaxf(m, __shfl_xor_sync(0xffffffffu, m, d));
    if (lane == 0) red[wrp] = m;
    __syncthreads();
    float mx = fmaxf(fmaxf(fmaxf(red[0], red[1]), fmaxf(red[2], red[3])),
                     fmaxf(fmaxf(red[4], red[5]), fmaxf(red[6], red[7])));
    __syncthreads();

    // block sum of exp
    float es = expf(s.x - mx) + expf(s.y - mx) + expf(s.z - mx) + expf(s.w - mx);
#pragma unroll
    for (int d = 16; d; d >>= 1) es += __shfl_xor_sync(0xffffffffu, es, d);
    if (lane == 0) red[wrp] = es;
    __syncthreads();
    float tot = red[0] + red[1] + red[2] + red[3] + red[4] + red[5] + red[6] + red[7];
    float lse = logf(tot) + mx;

    ((float4*)out)[b*(FF/4) + t] =
        make_float4(s.x - lse, s.y - lse, s.z - lse, s.w - lse);
}

// ---------------------------------------------------------------------------
extern "C" void kernel_launch(void* const* d_in, const int* in_sizes, int n_in,
                              void* d_out, int out_size) {
    const float *x = nullptr, *adj = nullptr, *W = nullptr, *a = nullptr;
    const float *fcw = nullptr, *fcb = nullptr;
    for (int i = 0; i < n_in; i++) {
        switch (in_sizes[i]) {
            case 458752:    x   = (const float*)d_in[i]; break;  // x (32,14,1024)
            case 6272:      adj = (const float*)d_in[i]; break;  // adj (32,14,14)
            case 134217728: W   = (const float*)d_in[i]; break;  // W (4,32,1024,1024)
            case 262144:    a   = (const float*)d_in[i]; break;  // a (4,32,2048,1)
            case 58720256:  fcw = (const float*)d_in[i]; break;  // fc_w (4,1024,14336)
            case 4096:      fcb = (const float*)d_in[i]; break;  // fc_b (4,1024)
        }
    }
    cudaFuncSetAttribute(k1, cudaFuncAttributeMaxDynamicSharedMemorySize, NN*FF*8);
    k1<<<HH*BB, 256, NN*FF*8>>>(x, W);
    k2<<<HH*BB, 448>>>(adj, a);
    k3<<<dim3(4, 4, 16), 128>>>(fcw);
    k4<<<BB, 256>>>(fcb, (float*)d_out);
}